// round 1
// baseline (speedup 1.0000x reference)
#include <cuda_runtime.h>
#include <cuda_bf16.h>

// Enframe: out[b, w, f] = in[b, f*HOP + w]
//   b in [0,16), w in [0,2048), f in [0,934)
//   FRAME=2048, HOP=512, FRAME/HOP = 4.
//
// Decompose w = q*512 + r  (q in [0,4), r in [0,512)):
//   out[b, q*512 + r, f] = in[b, (f+q)*512 + r]
// For fixed (b,q) this is a transpose of the input viewed as a
// [chunk][r] row-major matrix (chunk = sample/512) into [r][f].
// => 64 tiled 512x934 fp32 transposes; both global access sides coalesced.

#define SAMPLES     480000
#define HOP         512
#define FRAMES      934          // (480000 - 2048)/512 + 1
#define OUT_W       2048
#define TILE        32
#define BROWS       8

__global__ __launch_bounds__(TILE * BROWS)
void enframe_transpose_kernel(const float* __restrict__ in,
                              float* __restrict__ out) {
    __shared__ float tile[TILE][TILE + 1];   // +1 pad: conflict-free transpose

    const int bq = blockIdx.z;          // 0..63
    const int b  = bq >> 2;             // batch
    const int q  = bq & 3;              // which 512-block of w
    const int f0 = blockIdx.x * TILE;   // frame tile origin (f may be partial)
    const int r0 = blockIdx.y * TILE;   // within-hop offset tile (always full)

    const int tx = threadIdx.x;         // 0..31
    const int ty = threadIdx.y;         // 0..7

    const float* inb = in + (size_t)b * SAMPLES;

    // Load: element (f, r) = inb[(f+q)*HOP + r]; r contiguous -> coalesced.
    #pragma unroll
    for (int i = 0; i < TILE; i += BROWS) {
        int f = f0 + ty + i;
        if (f < FRAMES) {
            tile[ty + i][tx] = inb[(f + q) * HOP + r0 + tx];
        }
    }
    __syncthreads();

    // Store: out[b, q*512 + r, f]; f contiguous -> coalesced.
    float* outb = out + ((size_t)b * OUT_W + (size_t)q * HOP) * FRAMES;
    #pragma unroll
    for (int i = 0; i < TILE; i += BROWS) {
        int r = r0 + ty + i;
        int f = f0 + tx;
        if (f < FRAMES) {
            outb[(size_t)r * FRAMES + f] = tile[tx][ty + i];
        }
    }
}

extern "C" void kernel_launch(void* const* d_in, const int* in_sizes, int n_in,
                              void* d_out, int out_size) {
    const float* in = (const float*)d_in[0];
    float* out = (float*)d_out;

    dim3 block(TILE, BROWS);                       // 256 threads
    dim3 grid((FRAMES + TILE - 1) / TILE,          // 30 f-tiles
              HOP / TILE,                          // 16 r-tiles
              16 * 4);                             // b * q = 64
    enframe_transpose_kernel<<<grid, block>>>(in, out);
}

// round 3
// speedup vs baseline: 1.2714x; 1.2714x over previous
#include <cuda_runtime.h>
#include <cuda_bf16.h>

// Enframe: out[b, w, f] = in[b, f*HOP + w],  b<16, w<2048, f<934, HOP=512.
// w = q*512 + r  =>  out[b, q*512+r, f] = in[b, (f+q)*512 + r]
// => 64 independent 512x934 fp32 transposes (per (b,q)), 64x64 tiles.
//
// smem: tile[r_local][64], XOR-swizzled at float2 granularity:
//   logical column f of row r stored at float offset 2*((f>>1) ^ h(r)) + (f&1),
//   h(r) = (r>>2) & 31.
// Load:  LDG.128 + 4x STS.32   (conflict-free, 16B aligned)
// Store: LDS.64  + STG.64      (conflict-free, 8B aligned, coalesced)

#define SAMPLES 480000
#define HOP     512
#define FRAMES  934          // even
#define OUT_W   2048
#define TF      64
#define TR      64

__global__ __launch_bounds__(256)
void enframe_transpose_kernel(const float* __restrict__ in,
                              float* __restrict__ out) {
    __shared__ float tile[TR][TF];      // [r_local][swizzled f slots]

    const int bq = blockIdx.z;          // 0..63
    const int b  = bq >> 2;
    const int q  = bq & 3;
    const int f0 = blockIdx.x * TF;     // last f-tile partial (FRAMES=934)
    const int r0 = blockIdx.y * TR;

    const int tid = threadIdx.x;

    // ---- Load phase ----
    // thread -> rv = (tid&15)*4 (float4 column in r), fr = tid>>4 (f row step)
    {
        const int rv = (tid & 15) * 4;
        const int fr = tid >> 4;            // 0..15
        const int h  = (rv >> 2) & 31;      // same for rv..rv+3
        const float* inb = in + (size_t)b * SAMPLES + r0 + rv;

        if (f0 + TF <= FRAMES) {
            // fast path: batch all 4 LDG.128 for MLP, then scatter to smem
            float4 v[4];
            #pragma unroll
            for (int i = 0; i < 4; i++) {
                int f = f0 + fr + 16 * i;
                v[i] = *(const float4*)(inb + (size_t)(f + q) * HOP);
            }
            #pragma unroll
            for (int i = 0; i < 4; i++) {
                int fl  = fr + 16 * i;
                int off = 2 * ((fl >> 1) ^ h) + (fl & 1);
                tile[rv + 0][off] = v[i].x;
                tile[rv + 1][off] = v[i].y;
                tile[rv + 2][off] = v[i].z;
                tile[rv + 3][off] = v[i].w;
            }
        } else {
            #pragma unroll
            for (int i = 0; i < 4; i++) {
                int f = f0 + fr + 16 * i;
                if (f < FRAMES) {
                    float4 v = *(const float4*)(inb + (size_t)(f + q) * HOP);
                    int fl  = fr + 16 * i;
                    int off = 2 * ((fl >> 1) ^ h) + (fl & 1);
                    tile[rv + 0][off] = v.x;
                    tile[rv + 1][off] = v.y;
                    tile[rv + 2][off] = v.z;
                    tile[rv + 3][off] = v.w;
                }
            }
        }
    }
    __syncthreads();

    // ---- Store phase ----
    // lane l -> f pair (f0+2l, f0+2l+1); warp w -> r rows w, w+8, ...
    {
        const int l = tid & 31;
        const int w = tid >> 5;             // 0..7
        float* outb = out + ((size_t)b * OUT_W + (size_t)q * HOP) * FRAMES + f0;
        const bool ok = (f0 + 2 * l) < FRAMES;   // FRAMES even => pair valid
        #pragma unroll
        for (int i = 0; i < 8; i++) {
            int rl = w + 8 * i;
            int p  = l ^ ((rl >> 2) & 31);  // phys float2 slot of logical pair l
            if (ok) {
                float2 v = *(const float2*)&tile[rl][2 * p];
                *(float2*)(outb + (size_t)(r0 + rl) * FRAMES + 2 * l) = v;
            }
        }
    }
}

extern "C" void kernel_launch(void* const* d_in, const int* in_sizes, int n_in,
                              void* d_out, int out_size) {
    const float* in = (const float*)d_in[0];
    float* out = (float*)d_out;

    dim3 block(256);
    dim3 grid((FRAMES + TF - 1) / TF,     // 15 f-tiles
              HOP / TR,                   // 8 r-tiles
              16 * 4);                    // (b, q) pairs
    enframe_transpose_kernel<<<grid, block>>>(in, out);
}